// round 11
// baseline (speedup 1.0000x reference)
#include <cuda_runtime.h>
#include <math.h>

// Problem constants
#define BB 4
#define TT 2048
#define DD 512
#define HH 8
#define DH 64
#define LL 2
#define GG 64      // partial rows per batch (reduce & fused-gate emit blocks)
#define CHK 64     // gate-kernel blocks per batch (== GG)
#define EPSF 1e-5f

// Scratch (no device allocation allowed -> __device__ globals)
__device__ float g_part[BB][GG][DD];   // per-block partial sums of rstd*(x-mean)
__device__ float g_M[BB][HH][DD];      // folded per-head D-vectors
__device__ float g_S[BB][HH];          // sum_d M'
__device__ float g_bias[BB][HH];       // sum_d ln_b * M

// ---------------------------------------------------------------------------
// Kernel A: masked sum over tokens of rstd*(x - mean) (initial aud pass only)
// grid (GG, BB), 256 threads; warp batches 4 tokens; staged (atomic-free) fold
// ---------------------------------------------------------------------------
__global__ void k_reduce(const float* __restrict__ src,
                         const int* __restrict__ kpm) {
    int b = blockIdx.y;
    int blk = blockIdx.x;
    int tid = threadIdx.x;
    int warp = tid >> 5, lane = tid & 31;

    __shared__ float stg[8 * DD];   // 16 KB staging: warp-major strips

    int t0 = blk * 32 + warp * 4;
    const float4* base = (const float4*)(src + ((size_t)b * TT + t0) * DD);

    float4 v[4][4];
    float s[4], sq[4];
#pragma unroll
    for (int t = 0; t < 4; t++) {
        s[t] = 0.f; sq[t] = 0.f;
#pragma unroll
        for (int k = 0; k < 4; k++) {
            float4 x = base[t * 128 + k * 32 + lane];
            v[t][k] = x;
            s[t]  += x.x + x.y + x.z + x.w;
            sq[t] += x.x * x.x + x.y * x.y + x.z * x.z + x.w * x.w;
        }
    }
#pragma unroll
    for (int off = 16; off; off >>= 1) {
#pragma unroll
        for (int t = 0; t < 4; t++) {
            s[t]  += __shfl_xor_sync(0xffffffffu, s[t], off);
            sq[t] += __shfl_xor_sync(0xffffffffu, sq[t], off);
        }
    }
    float acc[16];
#pragma unroll
    for (int i = 0; i < 16; i++) acc[i] = 0.f;
#pragma unroll
    for (int t = 0; t < 4; t++) {
        if (kpm[(size_t)b * TT + t0 + t]) continue;
        float mean = s[t] * (1.f / DD);
        float var  = sq[t] * (1.f / DD) - mean * mean;
        float rstd = rsqrtf(var + EPSF);
        float sub  = rstd * mean;
#pragma unroll
        for (int k = 0; k < 4; k++) {
            acc[k * 4 + 0] += rstd * v[t][k].x - sub;
            acc[k * 4 + 1] += rstd * v[t][k].y - sub;
            acc[k * 4 + 2] += rstd * v[t][k].z - sub;
            acc[k * 4 + 3] += rstd * v[t][k].w - sub;
        }
    }
#pragma unroll
    for (int k = 0; k < 4; k++)
        *(float4*)&stg[warp * DD + k * 128 + lane * 4] =
            make_float4(acc[k * 4], acc[k * 4 + 1], acc[k * 4 + 2], acc[k * 4 + 3]);
    __syncthreads();
    float r0 = 0.f, r1 = 0.f;
#pragma unroll
    for (int w = 0; w < 8; w++) {
        r0 += stg[w * DD + tid];
        r1 += stg[w * DD + tid + 256];
    }
    g_part[b][blk][tid]       = r0;
    g_part[b][blk][tid + 256] = r1;
}

// ---------------------------------------------------------------------------
// Kernel B: per (b,h): inline source-mask count; c = g*acc + cnt*b ;
//           ksum = Wk_head @ c ; M' = (scale/valid)*g ⊙ (Wq^T @ ksum); S, bias
// grid BB*HH, 512 threads
// ---------------------------------------------------------------------------
__global__ void k_mid(const float* __restrict__ Wq, const float* __restrict__ Wk,
                      const float* __restrict__ lng, const float* __restrict__ lnb,
                      const int* __restrict__ src_kpm) {
    int b = blockIdx.x >> 3, h = blockIdx.x & 7;
    int tid = threadIdx.x;
    int warp = tid >> 5, lane = tid & 31;

    __shared__ float csh[DD];
    __shared__ float ksh[DH];
    __shared__ float rs[16], rb[16];
    __shared__ int cntsh[16];

    // inline mask count (coalesced, 4 ints/thread)
    int cnt = 0;
#pragma unroll
    for (int i = 0; i < 4; i++) cnt += (src_kpm[(size_t)b * TT + tid + i * 512] == 0);
#pragma unroll
    for (int off = 16; off; off >>= 1) cnt += __shfl_xor_sync(0xffffffffu, cnt, off);
    if (lane == 0) cntsh[warp] = cnt;

    float acc = 0.f;
#pragma unroll 8
    for (int g = 0; g < GG; g++) acc += g_part[b][g][tid];
    __syncthreads();

    int total = 0;
#pragma unroll
    for (int w = 0; w < 16; w++) total += cntsh[w];
    float validf = fmaxf((float)total, 1.0f);
    float cntf = (total == 0) ? 0.f : validf;

    csh[tid] = lng[tid] * acc + cntf * lnb[tid];
    __syncthreads();

#pragma unroll
    for (int jj = 0; jj < 4; jj++) {
        int j = warp * 4 + jj;
        const float* wk = Wk + (size_t)(h * DH + j) * DD;
        float s = 0.f;
#pragma unroll
        for (int k = 0; k < 16; k++) { int d = lane + 32 * k; s += csh[d] * wk[d]; }
#pragma unroll
        for (int off = 16; off; off >>= 1) s += __shfl_xor_sync(0xffffffffu, s, off);
        if (lane == 0) ksh[j] = s;
    }
    __syncthreads();

    float m = 0.f;
#pragma unroll
    for (int j = 0; j < DH; j++) m += ksh[j] * Wq[(size_t)(h * DH + j) * DD + tid];
    m *= 0.125f / validf;
    float mp = m * lng[tid];
    g_M[b][h][tid] = mp;

    float sv = mp, bv = lnb[tid] * m;
#pragma unroll
    for (int off = 16; off; off >>= 1) {
        sv += __shfl_xor_sync(0xffffffffu, sv, off);
        bv += __shfl_xor_sync(0xffffffffu, bv, off);
    }
    if (lane == 0) { rs[warp] = sv; rb[warp] = bv; }
    __syncthreads();
    if (tid == 0) {
        float S = 0.f, Bv = 0.f;
        for (int w = 0; w < 16; w++) { S += rs[w]; Bv += rb[w]; }
        g_S[b][h] = S;
        g_bias[b][h] = Bv;
    }
}

// ---------------------------------------------------------------------------
// Kernel C (fused): warp batches 4 tokens (full ILP), x re-read in epilogue
//   (L1-hot, warp-private rows). Inline source-mask count for the all-masked
//   flag. Butterfly reductions -> lane-parallel MLP. Atomic-free emit via
//   Msh staging. grid (CHK, BB), 256 threads, 3 blocks/SM.
// ---------------------------------------------------------------------------
__global__ void __launch_bounds__(256, 3)
k_gate(const float* __restrict__ xin, float* xout,
       const float* __restrict__ W1, const float* __restrict__ b1,
       const float* __restrict__ W2, const float* __restrict__ b2,
       const int* __restrict__ src_kpm, const int* __restrict__ emit_kpm,
       int emit) {
    int b = blockIdx.y, blk = blockIdx.x;
    int tid = threadIdx.x;
    int warp = tid >> 5, lane = tid & 31;

    __shared__ float Msh[HH * DD];             // 16 KB; reused as emit staging
    __shared__ float Ssh[HH], Bsh[HH];
    __shared__ float W1sh[128], b1sh[16], W2sh[16];
    __shared__ float b2sh;
    __shared__ int cntsh[8];

    {
        const float4* msrc = (const float4*)&g_M[b][0][0];
        float4* mdst = (float4*)&Msh[0];
#pragma unroll
        for (int i = 0; i < 4; i++) mdst[tid + i * 256] = msrc[tid + i * 256];
        if (tid < HH) { Ssh[tid] = g_S[b][tid]; Bsh[tid] = g_bias[b][tid]; }
        if (tid >= 32 && tid < 160) W1sh[tid - 32] = W1[tid - 32];
        if (tid >= 160 && tid < 176) b1sh[tid - 160] = b1[tid - 160];
        if (tid >= 176 && tid < 192) W2sh[tid - 176] = W2[tid - 176];
        if (tid == 192) b2sh = b2[0];
        // inline source-mask count (coalesced, 8 ints/thread)
        int cnt = 0;
#pragma unroll
        for (int i = 0; i < 8; i++) cnt += (src_kpm[(size_t)b * TT + tid + i * 256] == 0);
#pragma unroll
        for (int off = 16; off; off >>= 1) cnt += __shfl_xor_sync(0xffffffffu, cnt, off);
        if (lane == 0) cntsh[warp] = cnt;
    }
    __syncthreads();
    int total = 0;
#pragma unroll
    for (int w = 0; w < 8; w++) total += cntsh[w];
    int allsh = (total == 0);

    int t0 = blk * 32 + warp * 4;              // 4 consecutive tokens per warp
    const float4* base = (const float4*)(xin + ((size_t)b * TT + t0) * DD);
    float4* obase = (float4*)(xout + ((size_t)b * TT + t0) * DD);
    const float4* M4 = (const float4*)&Msh[0];
    int eidx = lane & 15;

    // ---- phase 1: stats + dots, x not retained ----
    float s[4], sq[4], dot[4][8];
#pragma unroll
    for (int t = 0; t < 4; t++) {
        s[t] = 0.f; sq[t] = 0.f;
#pragma unroll
        for (int h = 0; h < 8; h++) dot[t][h] = 0.f;
    }
#pragma unroll
    for (int k = 0; k < 4; k++) {
        float4 xv[4];
#pragma unroll
        for (int t = 0; t < 4; t++) {
            xv[t] = base[t * 128 + k * 32 + lane];
            s[t]  += xv[t].x + xv[t].y + xv[t].z + xv[t].w;
            sq[t] += xv[t].x * xv[t].x + xv[t].y * xv[t].y
                   + xv[t].z * xv[t].z + xv[t].w * xv[t].w;
        }
#pragma unroll
        for (int h = 0; h < 8; h++) {
            float4 mv = M4[h * 128 + k * 32 + lane];
#pragma unroll
            for (int t = 0; t < 4; t++) {
                dot[t][h] += xv[t].x * mv.x + xv[t].y * mv.y
                           + xv[t].z * mv.z + xv[t].w * mv.w;
            }
        }
    }
    // ---- phase 2: butterfly reductions (all lanes get full sums) ----
#pragma unroll
    for (int off = 16; off; off >>= 1) {
#pragma unroll
        for (int t = 0; t < 4; t++) {
            s[t]  += __shfl_xor_sync(0xffffffffu, s[t], off);
            sq[t] += __shfl_xor_sync(0xffffffffu, sq[t], off);
#pragma unroll
            for (int h = 0; h < 8; h++)
                dot[t][h] += __shfl_xor_sync(0xffffffffu, dot[t][h], off);
        }
    }
    // ---- phase 3: per-token gate (lane-parallel MLP, 4 chains interleaved) ----
    float mean[4], var[4], part[4];
#pragma unroll
    for (int t = 0; t < 4; t++) {
        mean[t] = s[t] * (1.f / DD);
        var[t]  = sq[t] * (1.f / DD) - mean[t] * mean[t];
        float rstd = rsqrtf(var[t] + EPSF);
        float a = b1sh[eidx];
#pragma unroll
        for (int h = 0; h < 8; h++) {
            float rel = rstd * (dot[t][h] - mean[t] * Ssh[h]) + Bsh[h];
            a += rel * W1sh[eidx * 8 + h];
        }
        part[t] = fmaxf(a, 0.f) * W2sh[eidx];
    }
#pragma unroll
    for (int off = 16; off; off >>= 1)
#pragma unroll
        for (int t = 0; t < 4; t++)
            part[t] += __shfl_xor_sync(0xffffffffu, part[t], off);

    float factor[4], rf[4], sub2[4];
#pragma unroll
    for (int t = 0; t < 4; t++) {
        float gacc = b2sh + 0.5f * part[t];
        float gate = 1.f / (1.f + expf(-gacc));
        if (allsh) gate = 0.f;
        factor[t] = 1.f + gate;
        float rstd2 = rsqrtf(factor[t] * factor[t] * var[t] + EPSF);
        rf[t]   = rstd2 * factor[t];
        sub2[t] = rf[t] * mean[t];
    }

    // ---- phase 4: re-read x (L1-hot), write out, accumulate emit partials ----
    float acc[16];
#pragma unroll
    for (int i = 0; i < 16; i++) acc[i] = 0.f;
#pragma unroll
    for (int t = 0; t < 4; t++) {
        int keep = emit ? (emit_kpm[(size_t)b * TT + t0 + t] == 0) : 0;
#pragma unroll
        for (int k = 0; k < 4; k++) {
            float4 x = base[t * 128 + k * 32 + lane];
            float4 o;
            o.x = x.x * factor[t]; o.y = x.y * factor[t];
            o.z = x.z * factor[t]; o.w = x.w * factor[t];
            obase[t * 128 + k * 32 + lane] = o;
            if (keep) {
                acc[k * 4 + 0] += rf[t] * x.x - sub2[t];
                acc[k * 4 + 1] += rf[t] * x.y - sub2[t];
                acc[k * 4 + 2] += rf[t] * x.z - sub2[t];
                acc[k * 4 + 3] += rf[t] * x.w - sub2[t];
            }
        }
    }

    if (emit) {
        __syncthreads();   // Msh reads done everywhere; reuse as staging
#pragma unroll
        for (int k = 0; k < 4; k++)
            *(float4*)&Msh[warp * DD + k * 128 + lane * 4] =
                make_float4(acc[k * 4], acc[k * 4 + 1], acc[k * 4 + 2], acc[k * 4 + 3]);
        __syncthreads();
        float r0 = 0.f, r1 = 0.f;
#pragma unroll
        for (int w = 0; w < 8; w++) {
            r0 += Msh[w * DD + tid];
            r1 += Msh[w * DD + tid + 256];
        }
        g_part[b][blk][tid]       = r0;
        g_part[b][blk][tid + 256] = r1;
    }
}

// ---------------------------------------------------------------------------
extern "C" void kernel_launch(void* const* d_in, const int* in_sizes, int n_in,
                              void* d_out, int out_size) {
    (void)in_sizes; (void)n_in; (void)out_size;
    const float* x_vid = (const float*)d_in[0];
    const float* x_aud = (const float*)d_in[1];
    const int* vid_kpm = (const int*)d_in[2];
    const int* aud_kpm = (const int*)d_in[3];
    const float* Wq_vid = (const float*)d_in[4];
    const float* Wk_aud = (const float*)d_in[5];
    const float* Wq_aud = (const float*)d_in[6];
    const float* Wk_vid = (const float*)d_in[7];
    const float* vgW1 = (const float*)d_in[8];
    const float* vgb1 = (const float*)d_in[9];
    const float* vgW2 = (const float*)d_in[10];
    const float* vgb2 = (const float*)d_in[11];
    const float* agW1 = (const float*)d_in[12];
    const float* agb1 = (const float*)d_in[13];
    const float* agW2 = (const float*)d_in[14];
    const float* agb2 = (const float*)d_in[15];
    const float* vid_g = (const float*)d_in[16];
    const float* vid_b = (const float*)d_in[17];
    const float* aud_g = (const float*)d_in[18];
    const float* aud_b = (const float*)d_in[19];

    const size_t N = (size_t)BB * TT * DD;
    float* out_vid = (float*)d_out;
    float* out_aud = out_vid + N;

    // initial source reduce: LN-sum of x_aud under aud mask
    k_reduce<<<dim3(GG, BB), 256>>>(x_aud, aud_kpm);

    const float* cur_vid = x_vid;
    const float* cur_aud = x_aud;
    for (int l = 0; l < LL; l++) {
        size_t wofs = (size_t)l * DD * DD;
        // --- vid stage: source = aud; gate vid; emit vid partials ---
        k_mid<<<BB * HH, 512>>>(Wq_vid + wofs, Wk_aud + wofs,
                                vid_g + (size_t)l * DD, vid_b + (size_t)l * DD,
                                aud_kpm);
        k_gate<<<dim3(CHK, BB), 256>>>(cur_vid, out_vid,
                                       vgW1 + (size_t)l * 128, vgb1 + (size_t)l * 16,
                                       vgW2 + (size_t)l * 16, vgb2 + l,
                                       aud_kpm, vid_kpm, 1);
        cur_vid = out_vid;
        // --- aud stage: source = updated vid; gate aud ---
        int emit_aud = (l < LL - 1) ? 1 : 0;
        k_mid<<<BB * HH, 512>>>(Wq_aud + wofs, Wk_vid + wofs,
                                aud_g + (size_t)l * DD, aud_b + (size_t)l * DD,
                                vid_kpm);
        k_gate<<<dim3(CHK, BB), 256>>>(cur_aud, out_aud,
                                       agW1 + (size_t)l * 128, agb1 + (size_t)l * 16,
                                       agW2 + (size_t)l * 16, agb2 + l,
                                       vid_kpm, aud_kpm, emit_aud);
        cur_aud = out_aud;
    }
}

// round 12
// speedup vs baseline: 1.4855x; 1.4855x over previous
#include <cuda_runtime.h>
#include <math.h>

// Problem constants
#define BB 4
#define TT 2048
#define DD 512
#define HH 8
#define DH 64
#define LL 2
#define GG 64      // partial rows per batch (reduce & fused-gate emit blocks)
#define CHK 64     // gate-kernel blocks per batch (== GG)
#define EPSF 1e-5f

// Scratch (no device allocation allowed -> __device__ globals)
__device__ float g_part[BB][GG][DD];   // per-block partial sums of rstd*(x-mean)
__device__ float g_M[BB][HH][DD];      // folded per-head D-vectors
__device__ float g_S[BB][HH];          // sum_d M'
__device__ float g_bias[BB][HH];       // sum_d ln_b * M

// ---------------------------------------------------------------------------
// Kernel A: masked sum over tokens of rstd*(x - mean) (initial aud pass only)
// grid (GG, BB), 256 threads; warp batches 4 tokens; staged (atomic-free) fold
// ---------------------------------------------------------------------------
__global__ void k_reduce(const float* __restrict__ src,
                         const int* __restrict__ kpm) {
    int b = blockIdx.y;
    int blk = blockIdx.x;
    int tid = threadIdx.x;
    int warp = tid >> 5, lane = tid & 31;

    __shared__ float stg[8 * DD];   // 16 KB staging: warp-major strips

    int t0 = blk * 32 + warp * 4;
    const float4* base = (const float4*)(src + ((size_t)b * TT + t0) * DD);

    float4 v[4][4];
    float s[4], sq[4];
#pragma unroll
    for (int t = 0; t < 4; t++) {
        s[t] = 0.f; sq[t] = 0.f;
#pragma unroll
        for (int k = 0; k < 4; k++) {
            float4 x = base[t * 128 + k * 32 + lane];
            v[t][k] = x;
            s[t]  += x.x + x.y + x.z + x.w;
            sq[t] += x.x * x.x + x.y * x.y + x.z * x.z + x.w * x.w;
        }
    }
#pragma unroll
    for (int off = 16; off; off >>= 1) {
#pragma unroll
        for (int t = 0; t < 4; t++) {
            s[t]  += __shfl_xor_sync(0xffffffffu, s[t], off);
            sq[t] += __shfl_xor_sync(0xffffffffu, sq[t], off);
        }
    }
    float acc[16];
#pragma unroll
    for (int i = 0; i < 16; i++) acc[i] = 0.f;
#pragma unroll
    for (int t = 0; t < 4; t++) {
        if (kpm[(size_t)b * TT + t0 + t]) continue;
        float mean = s[t] * (1.f / DD);
        float var  = sq[t] * (1.f / DD) - mean * mean;
        float rstd = rsqrtf(var + EPSF);
        float sub  = rstd * mean;
#pragma unroll
        for (int k = 0; k < 4; k++) {
            acc[k * 4 + 0] += rstd * v[t][k].x - sub;
            acc[k * 4 + 1] += rstd * v[t][k].y - sub;
            acc[k * 4 + 2] += rstd * v[t][k].z - sub;
            acc[k * 4 + 3] += rstd * v[t][k].w - sub;
        }
    }
#pragma unroll
    for (int k = 0; k < 4; k++)
        *(float4*)&stg[warp * DD + k * 128 + lane * 4] =
            make_float4(acc[k * 4], acc[k * 4 + 1], acc[k * 4 + 2], acc[k * 4 + 3]);
    __syncthreads();
    float r0 = 0.f, r1 = 0.f;
#pragma unroll
    for (int w = 0; w < 8; w++) {
        r0 += stg[w * DD + tid];
        r1 += stg[w * DD + tid + 256];
    }
    g_part[b][blk][tid]       = r0;
    g_part[b][blk][tid + 256] = r1;
}

// ---------------------------------------------------------------------------
// Kernel B: per (b,h): inline source-mask count; c = g*acc + cnt*b ;
//           ksum = Wk_head @ c ; M' = (scale/valid)*g ⊙ (Wq^T @ ksum); S, bias
// grid BB*HH, 512 threads
// ---------------------------------------------------------------------------
__global__ void k_mid(const float* __restrict__ Wq, const float* __restrict__ Wk,
                      const float* __restrict__ lng, const float* __restrict__ lnb,
                      const int* __restrict__ src_kpm) {
    int b = blockIdx.x >> 3, h = blockIdx.x & 7;
    int tid = threadIdx.x;
    int warp = tid >> 5, lane = tid & 31;

    __shared__ float csh[DD];
    __shared__ float ksh[DH];
    __shared__ float rs[16], rb[16];
    __shared__ int cntsh[16];

    // inline mask count (coalesced, 4 ints/thread)
    int cnt = 0;
#pragma unroll
    for (int i = 0; i < 4; i++) cnt += (src_kpm[(size_t)b * TT + tid + i * 512] == 0);
#pragma unroll
    for (int off = 16; off; off >>= 1) cnt += __shfl_xor_sync(0xffffffffu, cnt, off);
    if (lane == 0) cntsh[warp] = cnt;

    float acc = 0.f;
#pragma unroll 8
    for (int g = 0; g < GG; g++) acc += g_part[b][g][tid];
    __syncthreads();

    int total = 0;
#pragma unroll
    for (int w = 0; w < 16; w++) total += cntsh[w];
    float validf = fmaxf((float)total, 1.0f);
    float cntf = (total == 0) ? 0.f : validf;

    csh[tid] = lng[tid] * acc + cntf * lnb[tid];
    __syncthreads();

#pragma unroll
    for (int jj = 0; jj < 4; jj++) {
        int j = warp * 4 + jj;
        const float* wk = Wk + (size_t)(h * DH + j) * DD;
        float s = 0.f;
#pragma unroll
        for (int k = 0; k < 16; k++) { int d = lane + 32 * k; s += csh[d] * wk[d]; }
#pragma unroll
        for (int off = 16; off; off >>= 1) s += __shfl_xor_sync(0xffffffffu, s, off);
        if (lane == 0) ksh[j] = s;
    }
    __syncthreads();

    float m = 0.f;
#pragma unroll
    for (int j = 0; j < DH; j++) m += ksh[j] * Wq[(size_t)(h * DH + j) * DD + tid];
    m *= 0.125f / validf;
    float mp = m * lng[tid];
    g_M[b][h][tid] = mp;

    float sv = mp, bv = lnb[tid] * m;
#pragma unroll
    for (int off = 16; off; off >>= 1) {
        sv += __shfl_xor_sync(0xffffffffu, sv, off);
        bv += __shfl_xor_sync(0xffffffffu, bv, off);
    }
    if (lane == 0) { rs[warp] = sv; rb[warp] = bv; }
    __syncthreads();
    if (tid == 0) {
        float S = 0.f, Bv = 0.f;
        for (int w = 0; w < 16; w++) { S += rs[w]; Bv += rb[w]; }
        g_S[b][h] = S;
        g_bias[b][h] = Bv;
    }
}

// ---------------------------------------------------------------------------
// Kernel C (fused): proven R10 config — warp batches 4 tokens (full ILP),
//   x re-read in epilogue (L1-hot, warp-private rows), 128 regs / 2 blocks/SM.
//   Inline source-mask count. Butterfly reductions -> lane-parallel MLP.
//   Atomic-free emit via Msh staging. grid (CHK, BB), 256 threads.
// ---------------------------------------------------------------------------
__global__ void __launch_bounds__(256, 2)
k_gate(const float* __restrict__ xin, float* xout,
       const float* __restrict__ W1, const float* __restrict__ b1,
       const float* __restrict__ W2, const float* __restrict__ b2,
       const int* __restrict__ src_kpm, const int* __restrict__ emit_kpm,
       int emit) {
    int b = blockIdx.y, blk = blockIdx.x;
    int tid = threadIdx.x;
    int warp = tid >> 5, lane = tid & 31;

    __shared__ float Msh[HH * DD];             // 16 KB; reused as emit staging
    __shared__ float Ssh[HH], Bsh[HH];
    __shared__ float W1sh[128], b1sh[16], W2sh[16];
    __shared__ float b2sh;
    __shared__ int cntsh[8];

    {
        const float4* msrc = (const float4*)&g_M[b][0][0];
        float4* mdst = (float4*)&Msh[0];
#pragma unroll
        for (int i = 0; i < 4; i++) mdst[tid + i * 256] = msrc[tid + i * 256];
        if (tid < HH) { Ssh[tid] = g_S[b][tid]; Bsh[tid] = g_bias[b][tid]; }
        if (tid >= 32 && tid < 160) W1sh[tid - 32] = W1[tid - 32];
        if (tid >= 160 && tid < 176) b1sh[tid - 160] = b1[tid - 160];
        if (tid >= 176 && tid < 192) W2sh[tid - 176] = W2[tid - 176];
        if (tid == 192) b2sh = b2[0];
        // inline source-mask count (coalesced, 8 ints/thread)
        int cnt = 0;
#pragma unroll
        for (int i = 0; i < 8; i++) cnt += (src_kpm[(size_t)b * TT + tid + i * 256] == 0);
#pragma unroll
        for (int off = 16; off; off >>= 1) cnt += __shfl_xor_sync(0xffffffffu, cnt, off);
        if (lane == 0) cntsh[warp] = cnt;
    }
    __syncthreads();
    int total = 0;
#pragma unroll
    for (int w = 0; w < 8; w++) total += cntsh[w];
    int allsh = (total == 0);

    int t0 = blk * 32 + warp * 4;              // 4 consecutive tokens per warp
    const float4* base = (const float4*)(xin + ((size_t)b * TT + t0) * DD);
    float4* obase = (float4*)(xout + ((size_t)b * TT + t0) * DD);
    const float4* M4 = (const float4*)&Msh[0];
    int eidx = lane & 15;

    // ---- phase 1: stats + dots, x not retained ----
    float s[4], sq[4], dot[4][8];
#pragma unroll
    for (int t = 0; t < 4; t++) {
        s[t] = 0.f; sq[t] = 0.f;
#pragma unroll
        for (int h = 0; h < 8; h++) dot[t][h] = 0.f;
    }
#pragma unroll
    for (int k = 0; k < 4; k++) {
        float4 xv[4];
#pragma unroll
        for (int t = 0; t < 4; t++) {
            xv[t] = base[t * 128 + k * 32 + lane];
            s[t]  += xv[t].x + xv[t].y + xv[t].z + xv[t].w;
            sq[t] += xv[t].x * xv[t].x + xv[t].y * xv[t].y
                   + xv[t].z * xv[t].z + xv[t].w * xv[t].w;
        }
#pragma unroll
        for (int h = 0; h < 8; h++) {
            float4 mv = M4[h * 128 + k * 32 + lane];
#pragma unroll
            for (int t = 0; t < 4; t++) {
                dot[t][h] += xv[t].x * mv.x + xv[t].y * mv.y
                           + xv[t].z * mv.z + xv[t].w * mv.w;
            }
        }
    }
    // ---- phase 2: butterfly reductions (all lanes get full sums) ----
#pragma unroll
    for (int off = 16; off; off >>= 1) {
#pragma unroll
        for (int t = 0; t < 4; t++) {
            s[t]  += __shfl_xor_sync(0xffffffffu, s[t], off);
            sq[t] += __shfl_xor_sync(0xffffffffu, sq[t], off);
#pragma unroll
            for (int h = 0; h < 8; h++)
                dot[t][h] += __shfl_xor_sync(0xffffffffu, dot[t][h], off);
        }
    }
    // ---- phase 3: per-token gate (lane-parallel MLP, 4 chains interleaved) ----
    float mean[4], var[4], part[4];
#pragma unroll
    for (int t = 0; t < 4; t++) {
        mean[t] = s[t] * (1.f / DD);
        var[t]  = sq[t] * (1.f / DD) - mean[t] * mean[t];
        float rstd = rsqrtf(var[t] + EPSF);
        float a = b1sh[eidx];
#pragma unroll
        for (int h = 0; h < 8; h++) {
            float rel = rstd * (dot[t][h] - mean[t] * Ssh[h]) + Bsh[h];
            a += rel * W1sh[eidx * 8 + h];
        }
        part[t] = fmaxf(a, 0.f) * W2sh[eidx];
    }
#pragma unroll
    for (int off = 16; off; off >>= 1)
#pragma unroll
        for (int t = 0; t < 4; t++)
            part[t] += __shfl_xor_sync(0xffffffffu, part[t], off);

    float factor[4], rf[4], sub2[4];
#pragma unroll
    for (int t = 0; t < 4; t++) {
        float gacc = b2sh + 0.5f * part[t];
        float gate = 1.f / (1.f + expf(-gacc));
        if (allsh) gate = 0.f;
        factor[t] = 1.f + gate;
        float rstd2 = rsqrtf(factor[t] * factor[t] * var[t] + EPSF);
        rf[t]   = rstd2 * factor[t];
        sub2[t] = rf[t] * mean[t];
    }

    // ---- phase 4: re-read x (L1-hot), write out, accumulate emit partials ----
    float acc[16];
#pragma unroll
    for (int i = 0; i < 16; i++) acc[i] = 0.f;
#pragma unroll
    for (int t = 0; t < 4; t++) {
        int keep = emit ? (emit_kpm[(size_t)b * TT + t0 + t] == 0) : 0;
#pragma unroll
        for (int k = 0; k < 4; k++) {
            float4 x = base[t * 128 + k * 32 + lane];
            float4 o;
            o.x = x.x * factor[t]; o.y = x.y * factor[t];
            o.z = x.z * factor[t]; o.w = x.w * factor[t];
            obase[t * 128 + k * 32 + lane] = o;
            if (keep) {
                acc[k * 4 + 0] += rf[t] * x.x - sub2[t];
                acc[k * 4 + 1] += rf[t] * x.y - sub2[t];
                acc[k * 4 + 2] += rf[t] * x.z - sub2[t];
                acc[k * 4 + 3] += rf[t] * x.w - sub2[t];
            }
        }
    }

    if (emit) {
        __syncthreads();   // Msh reads done everywhere; reuse as staging
#pragma unroll
        for (int k = 0; k < 4; k++)
            *(float4*)&Msh[warp * DD + k * 128 + lane * 4] =
                make_float4(acc[k * 4], acc[k * 4 + 1], acc[k * 4 + 2], acc[k * 4 + 3]);
        __syncthreads();
        float r0 = 0.f, r1 = 0.f;
#pragma unroll
        for (int w = 0; w < 8; w++) {
            r0 += Msh[w * DD + tid];
            r1 += Msh[w * DD + tid + 256];
        }
        g_part[b][blk][tid]       = r0;
        g_part[b][blk][tid + 256] = r1;
    }
}

// ---------------------------------------------------------------------------
extern "C" void kernel_launch(void* const* d_in, const int* in_sizes, int n_in,
                              void* d_out, int out_size) {
    (void)in_sizes; (void)n_in; (void)out_size;
    const float* x_vid = (const float*)d_in[0];
    const float* x_aud = (const float*)d_in[1];
    const int* vid_kpm = (const int*)d_in[2];
    const int* aud_kpm = (const int*)d_in[3];
    const float* Wq_vid = (const float*)d_in[4];
    const float* Wk_aud = (const float*)d_in[5];
    const float* Wq_aud = (const float*)d_in[6];
    const float* Wk_vid = (const float*)d_in[7];
    const float* vgW1 = (const float*)d_in[8];
    const float* vgb1 = (const float*)d_in[9];
    const float* vgW2 = (const float*)d_in[10];
    const float* vgb2 = (const float*)d_in[11];
    const float* agW1 = (const float*)d_in[12];
    const float* agb1 = (const float*)d_in[13];
    const float* agW2 = (const float*)d_in[14];
    const float* agb2 = (const float*)d_in[15];
    const float* vid_g = (const float*)d_in[16];
    const float* vid_b = (const float*)d_in[17];
    const float* aud_g = (const float*)d_in[18];
    const float* aud_b = (const float*)d_in[19];

    const size_t N = (size_t)BB * TT * DD;
    float* out_vid = (float*)d_out;
    float* out_aud = out_vid + N;

    // initial source reduce: LN-sum of x_aud under aud mask
    k_reduce<<<dim3(GG, BB), 256>>>(x_aud, aud_kpm);

    const float* cur_vid = x_vid;
    const float* cur_aud = x_aud;
    for (int l = 0; l < LL; l++) {
        size_t wofs = (size_t)l * DD * DD;
        // --- vid stage: source = aud; gate vid; emit vid partials ---
        k_mid<<<BB * HH, 512>>>(Wq_vid + wofs, Wk_aud + wofs,
                                vid_g + (size_t)l * DD, vid_b + (size_t)l * DD,
                                aud_kpm);
        k_gate<<<dim3(CHK, BB), 256>>>(cur_vid, out_vid,
                                       vgW1 + (size_t)l * 128, vgb1 + (size_t)l * 16,
                                       vgW2 + (size_t)l * 16, vgb2 + l,
                                       aud_kpm, vid_kpm, 1);
        cur_vid = out_vid;
        // --- aud stage: source = updated vid; gate aud ---
        int emit_aud = (l < LL - 1) ? 1 : 0;
        k_mid<<<BB * HH, 512>>>(Wq_aud + wofs, Wk_vid + wofs,
                                aud_g + (size_t)l * DD, aud_b + (size_t)l * DD,
                                vid_kpm);
        k_gate<<<dim3(CHK, BB), 256>>>(cur_aud, out_aud,
                                       agW1 + (size_t)l * 128, agb1 + (size_t)l * 16,
                                       agW2 + (size_t)l * 16, agb2 + l,
                                       vid_kpm, aud_kpm, emit_aud);
        cur_aud = out_aud;
    }
}

// round 14
// speedup vs baseline: 1.8234x; 1.2275x over previous
#include <cuda_runtime.h>
#include <math.h>

// Problem constants
#define BB 4
#define TT 2048
#define DD 512
#define HH 8
#define DH 64
#define LL 2
#define GG 64      // partial rows per batch (reduce & fused-gate emit blocks)
#define CHK 64     // gate-kernel blocks per batch (== GG)
#define EPSF 1e-5f

// Scratch (no device allocation allowed -> __device__ globals)
__device__ float g_part[BB][GG][DD];   // per-block partial sums of rstd*(x-mean)
__device__ float g_M[BB][HH][DD];      // folded per-head D-vectors
__device__ float g_S[BB][HH];          // sum_d M'
__device__ float g_bias[BB][HH];       // sum_d ln_b * M
__device__ float g_valid[2][BB];       // clipped valid counts: [0]=vid, [1]=aud
__device__ int   g_all[2][BB];         // all-masked flags

// ---------------------------------------------------------------------------
// Pairwise-packed warp all-reduce: full-warp sums of BOTH a and b delivered
// to ALL lanes in 6 shfl (vs 10). hi = (lane & 16).
//   pack: low half carries a-identity, high half carries b-identity
//   4 butterfly levels within each xor-closed 16-lane half
//   final off=16 exchange returns the other sum
// ---------------------------------------------------------------------------
__device__ __forceinline__ void wsum2(float a, float b, float& sa, float& sb,
                                      unsigned hi) {
    float t = __shfl_xor_sync(0xffffffffu, hi ? a : b, 16);
    float r = (hi ? b : a) + t;
    r += __shfl_xor_sync(0xffffffffu, r, 8);
    r += __shfl_xor_sync(0xffffffffu, r, 4);
    r += __shfl_xor_sync(0xffffffffu, r, 2);
    r += __shfl_xor_sync(0xffffffffu, r, 1);
    float o = __shfl_xor_sync(0xffffffffu, r, 16);
    sa = hi ? o : r;
    sb = hi ? r : o;
}

// Packed variant without unpack: ALL low-half lanes end with sum(a),
// ALL high-half lanes end with sum(b). 5 shfl.
__device__ __forceinline__ float wsum2_packed(float a, float b, unsigned hi) {
    float t = __shfl_xor_sync(0xffffffffu, hi ? a : b, 16);
    float r = (hi ? b : a) + t;
    r += __shfl_xor_sync(0xffffffffu, r, 8);
    r += __shfl_xor_sync(0xffffffffu, r, 4);
    r += __shfl_xor_sync(0xffffffffu, r, 2);
    r += __shfl_xor_sync(0xffffffffu, r, 1);
    return r;
}

// ---------------------------------------------------------------------------
// Kernel A: masked sum over tokens of rstd*(x - mean) (initial aud pass only)
// grid (GG+2, BB): blocks [0,GG) do the reduce; blocks GG,GG+1 compute the
// mask statistics (folded k_counts -- dedicated blocks, zero hot-path cost).
// ---------------------------------------------------------------------------
__global__ void k_reduce(const float* __restrict__ src,
                         const int* __restrict__ kpm,
                         const int* __restrict__ vid_kpm,
                         const int* __restrict__ aud_kpm) {
    int b = blockIdx.y;
    int blk = blockIdx.x;
    int tid = threadIdx.x;
    int warp = tid >> 5, lane = tid & 31;
    unsigned hi = lane & 16;

    __shared__ float stg[8 * DD];   // 16 KB staging: warp-major strips

    if (blk >= GG) {                // ---- mask-statistics blocks ----
        int m = blk - GG;           // 0 = vid mask, 1 = aud mask
        const int* kp = (m == 0 ? vid_kpm : aud_kpm) + (size_t)b * TT;
        int cnt = 0;
#pragma unroll
        for (int i = 0; i < 8; i++) cnt += (kp[tid + i * 256] == 0);
#pragma unroll
        for (int off = 16; off; off >>= 1)
            cnt += __shfl_xor_sync(0xffffffffu, cnt, off);
        __shared__ int csh[8];
        if (lane == 0) csh[warp] = cnt;
        __syncthreads();
        if (tid == 0) {
            int c = 0;
            for (int w = 0; w < 8; w++) c += csh[w];
            g_valid[m][b] = fmaxf((float)c, 1.0f);
            g_all[m][b] = (c == 0) ? 1 : 0;
        }
        return;
    }

    int t0 = blk * 32 + warp * 4;
    const float4* base = (const float4*)(src + ((size_t)b * TT + t0) * DD);

    float4 v[4][4];
    float s[4], sq[4];
#pragma unroll
    for (int t = 0; t < 4; t++) {
        s[t] = 0.f; sq[t] = 0.f;
#pragma unroll
        for (int k = 0; k < 4; k++) {
            float4 x = base[t * 128 + k * 32 + lane];
            v[t][k] = x;
            s[t]  += x.x + x.y + x.z + x.w;
            sq[t] += x.x * x.x + x.y * x.y + x.z * x.z + x.w * x.w;
        }
    }
#pragma unroll
    for (int t = 0; t < 4; t++) wsum2(s[t], sq[t], s[t], sq[t], hi);

    float acc[16];
#pragma unroll
    for (int i = 0; i < 16; i++) acc[i] = 0.f;
#pragma unroll
    for (int t = 0; t < 4; t++) {
        if (kpm[(size_t)b * TT + t0 + t]) continue;
        float mean = s[t] * (1.f / DD);
        float var  = sq[t] * (1.f / DD) - mean * mean;
        float rstd = rsqrtf(var + EPSF);
        float sub  = rstd * mean;
#pragma unroll
        for (int k = 0; k < 4; k++) {
            acc[k * 4 + 0] += rstd * v[t][k].x - sub;
            acc[k * 4 + 1] += rstd * v[t][k].y - sub;
            acc[k * 4 + 2] += rstd * v[t][k].z - sub;
            acc[k * 4 + 3] += rstd * v[t][k].w - sub;
        }
    }
#pragma unroll
    for (int k = 0; k < 4; k++)
        *(float4*)&stg[warp * DD + k * 128 + lane * 4] =
            make_float4(acc[k * 4], acc[k * 4 + 1], acc[k * 4 + 2], acc[k * 4 + 3]);
    __syncthreads();
    float r0 = 0.f, r1 = 0.f;
#pragma unroll
    for (int w = 0; w < 8; w++) {
        r0 += stg[w * DD + tid];
        r1 += stg[w * DD + tid + 256];
    }
    g_part[b][blk][tid]       = r0;
    g_part[b][blk][tid + 256] = r1;
}

// ---------------------------------------------------------------------------
// Kernel B: per (b,h): c = g*acc + cnt*b ; ksum = Wk_head @ c ;
//           M' = (scale/valid) * g ⊙ (Wq_head^T @ ksum) ; plus S, bias
// grid BB*HH, 512 threads
// ---------------------------------------------------------------------------
__global__ void k_mid(const float* __restrict__ Wq, const float* __restrict__ Wk,
                      const float* __restrict__ lng, const float* __restrict__ lnb,
                      int srcm) {
    int b = blockIdx.x >> 3, h = blockIdx.x & 7;
    int tid = threadIdx.x;
    int warp = tid >> 5, lane = tid & 31;
    unsigned hi = lane & 16;

    __shared__ float csh[DD];
    __shared__ float ksh[DH];
    __shared__ float rs[16], rb[16];

    float validf = g_valid[srcm][b];
    float cntf = g_all[srcm][b] ? 0.f : validf;

    float acc = 0.f;
#pragma unroll 8
    for (int g = 0; g < GG; g++) acc += g_part[b][g][tid];
    csh[tid] = lng[tid] * acc + cntf * lnb[tid];
    __syncthreads();

    // 4 rows per warp: compute partials, then packed pair-reduce
    float rowp[4];
#pragma unroll
    for (int jj = 0; jj < 4; jj++) {
        int j = warp * 4 + jj;
        const float* wk = Wk + (size_t)(h * DH + j) * DD;
        float s = 0.f;
#pragma unroll
        for (int k = 0; k < 16; k++) { int d = lane + 32 * k; s += csh[d] * wk[d]; }
        rowp[jj] = s;
    }
    float ra = wsum2_packed(rowp[0], rowp[1], hi);
    float rc = wsum2_packed(rowp[2], rowp[3], hi);
    if (lane == 0)       { ksh[warp * 4 + 0] = ra; ksh[warp * 4 + 2] = rc; }
    else if (lane == 16) { ksh[warp * 4 + 1] = ra; ksh[warp * 4 + 3] = rc; }
    __syncthreads();

    float m = 0.f;
#pragma unroll
    for (int j = 0; j < DH; j++) m += ksh[j] * Wq[(size_t)(h * DH + j) * DD + tid];
    m *= 0.125f / validf;
    float mp = m * lng[tid];
    g_M[b][h][tid] = mp;

    float r = wsum2_packed(mp, lnb[tid] * m, hi);
    if (lane == 0)       rs[warp] = r;
    else if (lane == 16) rb[warp] = r;
    __syncthreads();
    if (tid == 0) {
        float S = 0.f, Bv = 0.f;
        for (int w = 0; w < 16; w++) { S += rs[w]; Bv += rb[w]; }
        g_S[b][h] = S;
        g_bias[b][h] = Bv;
    }
}

// ---------------------------------------------------------------------------
// Kernel C (fused): proven R10 config — warp batches 4 tokens (full ILP),
//   x re-read in epilogue (L1-hot, warp-private rows), 2 blocks/SM.
//   Pairwise-packed warp reductions (132 vs 220 shfl) -> lane-parallel MLP.
//   Atomic-free emit via Msh staging. grid (CHK, BB), 256 threads.
// ---------------------------------------------------------------------------
__global__ void __launch_bounds__(256, 2)
k_gate(const float* __restrict__ xin, float* xout,
       const float* __restrict__ W1, const float* __restrict__ b1,
       const float* __restrict__ W2, const float* __restrict__ b2,
       int srcm, const int* __restrict__ emit_kpm, int emit) {
    int b = blockIdx.y, blk = blockIdx.x;
    int tid = threadIdx.x;
    int warp = tid >> 5, lane = tid & 31;
    unsigned hi = lane & 16;

    __shared__ float Msh[HH * DD];             // 16 KB; reused as emit staging
    __shared__ float Ssh[HH], Bsh[HH];
    __shared__ float W1sh[128], b1sh[16], W2sh[16];
    __shared__ float b2sh;
    __shared__ int allsh;

    {
        const float4* msrc = (const float4*)&g_M[b][0][0];
        float4* mdst = (float4*)&Msh[0];
#pragma unroll
        for (int i = 0; i < 4; i++) mdst[tid + i * 256] = msrc[tid + i * 256];
        if (tid < HH) { Ssh[tid] = g_S[b][tid]; Bsh[tid] = g_bias[b][tid]; }
        if (tid >= 32 && tid < 160) W1sh[tid - 32] = W1[tid - 32];
        if (tid >= 160 && tid < 176) b1sh[tid - 160] = b1[tid - 160];
        if (tid >= 176 && tid < 192) W2sh[tid - 176] = W2[tid - 176];
        if (tid == 192) b2sh = b2[0];
        if (tid == 193) allsh = g_all[srcm][b];
    }
    __syncthreads();

    int t0 = blk * 32 + warp * 4;              // 4 consecutive tokens per warp
    const float4* base = (const float4*)(xin + ((size_t)b * TT + t0) * DD);
    float4* obase = (float4*)(xout + ((size_t)b * TT + t0) * DD);
    const float4* M4 = (const float4*)&Msh[0];
    int eidx = lane & 15;

    // ---- phase 1: stats + dots, x not retained ----
    float s[4], sq[4], dot[4][8];
#pragma unroll
    for (int t = 0; t < 4; t++) {
        s[t] = 0.f; sq[t] = 0.f;
#pragma unroll
        for (int h = 0; h < 8; h++) dot[t][h] = 0.f;
    }
#pragma unroll
    for (int k = 0; k < 4; k++) {
        float4 xv[4];
#pragma unroll
        for (int t = 0; t < 4; t++) {
            xv[t] = base[t * 128 + k * 32 + lane];
            s[t]  += xv[t].x + xv[t].y + xv[t].z + xv[t].w;
            sq[t] += xv[t].x * xv[t].x + xv[t].y * xv[t].y
                   + xv[t].z * xv[t].z + xv[t].w * xv[t].w;
        }
#pragma unroll
        for (int h = 0; h < 8; h++) {
            float4 mv = M4[h * 128 + k * 32 + lane];
#pragma unroll
            for (int t = 0; t < 4; t++) {
                dot[t][h] += xv[t].x * mv.x + xv[t].y * mv.y
                           + xv[t].z * mv.z + xv[t].w * mv.w;
            }
        }
    }
    // ---- phase 2: pairwise-packed warp all-reduces ----
#pragma unroll
    for (int t = 0; t < 4; t++) {
        wsum2(s[t], sq[t], s[t], sq[t], hi);
#pragma unroll
        for (int i = 0; i < 4; i++)
            wsum2(dot[t][i], dot[t][i + 4], dot[t][i], dot[t][i + 4], hi);
    }
    // ---- phase 3: per-token gate (lane-parallel MLP, 4 chains interleaved) ----
    float mean[4], var[4], part[4];
#pragma unroll
    for (int t = 0; t < 4; t++) {
        mean[t] = s[t] * (1.f / DD);
        var[t]  = sq[t] * (1.f / DD) - mean[t] * mean[t];
        float rstd = rsqrtf(var[t] + EPSF);
        float a = b1sh[eidx];
#pragma unroll
        for (int h = 0; h < 8; h++) {
            float rel = rstd * (dot[t][h] - mean[t] * Ssh[h]) + Bsh[h];
            a += rel * W1sh[eidx * 8 + h];
        }
        part[t] = fmaxf(a, 0.f) * W2sh[eidx];
    }
    wsum2(part[0], part[1], part[0], part[1], hi);
    wsum2(part[2], part[3], part[2], part[3], hi);

    float factor[4], rf[4], sub2[4];
#pragma unroll
    for (int t = 0; t < 4; t++) {
        float gacc = b2sh + 0.5f * part[t];   // each unit counted twice over 32 lanes
        float gate = 1.f / (1.f + expf(-gacc));
        if (allsh) gate = 0.f;
        factor[t] = 1.f + gate;
        float rstd2 = rsqrtf(factor[t] * factor[t] * var[t] + EPSF);
        rf[t]   = rstd2 * factor[t];
        sub2[t] = rf[t] * mean[t];
    }

    // ---- phase 4: re-read x (L1-hot), write out, accumulate emit partials ----
    float acc[16];
#pragma unroll
    for (int i = 0; i < 16; i++) acc[i] = 0.f;
#pragma unroll
    for (int t = 0; t < 4; t++) {
        int keep = emit ? (emit_kpm[(size_t)b * TT + t0 + t] == 0) : 0;
#pragma unroll
        for (int k = 0; k < 4; k++) {
            float4 x = base[t * 128 + k * 32 + lane];
            float4 o;
            o.x = x.x * factor[t]; o.y = x.y * factor[t];
            o.z = x.z * factor[t]; o.w = x.w * factor[t];
            obase[t * 128 + k * 32 + lane] = o;
            if (keep) {
                acc[k * 4 + 0] += rf[t] * x.x - sub2[t];
                acc[k * 4 + 1] += rf[t] * x.y - sub2[t];
                acc[k * 4 + 2] += rf[t] * x.z - sub2[t];
                acc[k * 4 + 3] += rf[t] * x.w - sub2[t];
            }
        }
    }

    if (emit) {
        __syncthreads();   // Msh reads done everywhere; reuse as staging
#pragma unroll
        for (int k = 0; k < 4; k++)
            *(float4*)&Msh[warp * DD + k * 128 + lane * 4] =
                make_float4(acc[k * 4], acc[k * 4 + 1], acc[k * 4 + 2], acc[k * 4 + 3]);
        __syncthreads();
        float r0 = 0.f, r1 = 0.f;
#pragma unroll
        for (int w = 0; w < 8; w++) {
            r0 += Msh[w * DD + tid];
            r1 += Msh[w * DD + tid + 256];
        }
        g_part[b][blk][tid]       = r0;
        g_part[b][blk][tid + 256] = r1;
    }
}

// ---------------------------------------------------------------------------
extern "C" void kernel_launch(void* const* d_in, const int* in_sizes, int n_in,
                              void* d_out, int out_size) {
    (void)in_sizes; (void)n_in; (void)out_size;
    const float* x_vid = (const float*)d_in[0];
    const float* x_aud = (const float*)d_in[1];
    const int* vid_kpm = (const int*)d_in[2];
    const int* aud_kpm = (const int*)d_in[3];
    const float* Wq_vid = (const float*)d_in[4];
    const float* Wk_aud = (const float*)d_in[5];
    const float* Wq_aud = (const float*)d_in[6];
    const float* Wk_vid = (const float*)d_in[7];
    const float* vgW1 = (const float*)d_in[8];
    const float* vgb1 = (const float*)d_in[9];
    const float* vgW2 = (const float*)d_in[10];
    const float* vgb2 = (const float*)d_in[11];
    const float* agW1 = (const float*)d_in[12];
    const float* agb1 = (const float*)d_in[13];
    const float* agW2 = (const float*)d_in[14];
    const float* agb2 = (const float*)d_in[15];
    const float* vid_g = (const float*)d_in[16];
    const float* vid_b = (const float*)d_in[17];
    const float* aud_g = (const float*)d_in[18];
    const float* aud_b = (const float*)d_in[19];

    const size_t N = (size_t)BB * TT * DD;
    float* out_vid = (float*)d_out;
    float* out_aud = out_vid + N;

    // initial source reduce (LN-sum of x_aud under aud mask) + mask stats
    k_reduce<<<dim3(GG + 2, BB), 256>>>(x_aud, aud_kpm, vid_kpm, aud_kpm);

    const float* cur_vid = x_vid;
    const float* cur_aud = x_aud;
    for (int l = 0; l < LL; l++) {
        size_t wofs = (size_t)l * DD * DD;
        // --- vid stage: source = aud (mask 1); gate vid; emit vid partials ---
        k_mid<<<BB * HH, 512>>>(Wq_vid + wofs, Wk_aud + wofs,
                                vid_g + (size_t)l * DD, vid_b + (size_t)l * DD, 1);
        k_gate<<<dim3(CHK, BB), 256>>>(cur_vid, out_vid,
                                       vgW1 + (size_t)l * 128, vgb1 + (size_t)l * 16,
                                       vgW2 + (size_t)l * 16, vgb2 + l, 1,
                                       vid_kpm, 1);
        cur_vid = out_vid;
        // --- aud stage: source = updated vid (mask 0); gate aud ---
        int emit_aud = (l < LL - 1) ? 1 : 0;
        k_mid<<<BB * HH, 512>>>(Wq_aud + wofs, Wk_vid + wofs,
                                aud_g + (size_t)l * DD, aud_b + (size_t)l * DD, 0);
        k_gate<<<dim3(CHK, BB), 256>>>(cur_aud, out_aud,
                                       agW1 + (size_t)l * 128, agb1 + (size_t)l * 16,
                                       agW2 + (size_t)l * 16, agb2 + l, 0,
                                       aud_kpm, emit_aud);
        cur_aud = out_aud;
    }
}

// round 16
// speedup vs baseline: 1.8242x; 1.0004x over previous
#include <cuda_runtime.h>
#include <math.h>

// Problem constants
#define BB 4
#define TT 2048
#define DD 512
#define HH 8
#define DH 64
#define LL 2
#define GG 64      // partial rows per batch (reduce & fused-gate emit blocks)
#define EPSF 1e-5f
#define NMID 32    // mid blocks per fused stage

// Scratch (no device allocation allowed -> __device__ globals)
__device__ float g_part[BB][GG][DD];   // per-block partial sums of rstd*(x-mean)
__device__ float g_M[BB][HH][DD];      // folded per-head D-vectors
__device__ float g_S[BB][HH];          // sum_d M'
__device__ float g_bias[BB][HH];       // sum_d ln_b * M
__device__ float g_valid[2][BB];       // clipped valid counts: [0]=vid, [1]=aud
__device__ int   g_all[2][BB];         // all-masked flags
__device__ int   g_flag[4];            // per-stage mid-done fan-in counters

// ---------------------------------------------------------------------------
// Pairwise-packed warp all-reduce: full-warp sums of BOTH a and b delivered
// to ALL lanes in 6 shfl. hi = (lane & 16).
// ---------------------------------------------------------------------------
__device__ __forceinline__ void wsum2(float a, float b, float& sa, float& sb,
                                      unsigned hi) {
    float t = __shfl_xor_sync(0xffffffffu, hi ? a : b, 16);
    float r = (hi ? b : a) + t;
    r += __shfl_xor_sync(0xffffffffu, r, 8);
    r += __shfl_xor_sync(0xffffffffu, r, 4);
    r += __shfl_xor_sync(0xffffffffu, r, 2);
    r += __shfl_xor_sync(0xffffffffu, r, 1);
    float o = __shfl_xor_sync(0xffffffffu, r, 16);
    sa = hi ? o : r;
    sb = hi ? r : o;
}

// Packed variant: low-half lanes end with sum(a), high-half with sum(b). 5 shfl.
__device__ __forceinline__ float wsum2_packed(float a, float b, unsigned hi) {
    float t = __shfl_xor_sync(0xffffffffu, hi ? a : b, 16);
    float r = (hi ? b : a) + t;
    r += __shfl_xor_sync(0xffffffffu, r, 8);
    r += __shfl_xor_sync(0xffffffffu, r, 4);
    r += __shfl_xor_sync(0xffffffffu, r, 2);
    r += __shfl_xor_sync(0xffffffffu, r, 1);
    return r;
}

// ---------------------------------------------------------------------------
// Kernel A: masked sum over tokens of rstd*(x - mean) (initial aud pass only)
// grid (GG+2, BB): blocks [0,GG) reduce; blocks GG,GG+1 do mask stats and
// reset the per-stage fan-in flags (this kernel is always the first node).
// ---------------------------------------------------------------------------
__global__ void k_reduce(const float* __restrict__ src,
                         const int* __restrict__ kpm,
                         const int* __restrict__ vid_kpm,
                         const int* __restrict__ aud_kpm) {
    int b = blockIdx.y;
    int blk = blockIdx.x;
    int tid = threadIdx.x;
    int warp = tid >> 5, lane = tid & 31;
    unsigned hi = lane & 16;

    __shared__ float stg[8 * DD];   // 16 KB staging: warp-major strips

    if (blk >= GG) {                // ---- mask-statistics blocks ----
        int m = blk - GG;           // 0 = vid mask, 1 = aud mask
        if (m == 0 && b == 0 && tid >= 32 && tid < 36) g_flag[tid - 32] = 0;
        const int* kp = (m == 0 ? vid_kpm : aud_kpm) + (size_t)b * TT;
        int cnt = 0;
#pragma unroll
        for (int i = 0; i < 8; i++) cnt += (kp[tid + i * 256] == 0);
#pragma unroll
        for (int off = 16; off; off >>= 1)
            cnt += __shfl_xor_sync(0xffffffffu, cnt, off);
        __shared__ int csh_i[8];
        if (lane == 0) csh_i[warp] = cnt;
        __syncthreads();
        if (tid == 0) {
            int c = 0;
            for (int w = 0; w < 8; w++) c += csh_i[w];
            g_valid[m][b] = fmaxf((float)c, 1.0f);
            g_all[m][b] = (c == 0) ? 1 : 0;
        }
        return;
    }

    int t0 = blk * 32 + warp * 4;
    const float4* base = (const float4*)(src + ((size_t)b * TT + t0) * DD);

    float4 v[4][4];
    float s[4], sq[4];
#pragma unroll
    for (int t = 0; t < 4; t++) {
        s[t] = 0.f; sq[t] = 0.f;
#pragma unroll
        for (int k = 0; k < 4; k++) {
            float4 x = base[t * 128 + k * 32 + lane];
            v[t][k] = x;
            s[t]  += x.x + x.y + x.z + x.w;
            sq[t] += x.x * x.x + x.y * x.y + x.z * x.z + x.w * x.w;
        }
    }
#pragma unroll
    for (int t = 0; t < 4; t++) wsum2(s[t], sq[t], s[t], sq[t], hi);

    float acc[16];
#pragma unroll
    for (int i = 0; i < 16; i++) acc[i] = 0.f;
#pragma unroll
    for (int t = 0; t < 4; t++) {
        if (kpm[(size_t)b * TT + t0 + t]) continue;
        float mean = s[t] * (1.f / DD);
        float var  = sq[t] * (1.f / DD) - mean * mean;
        float rstd = rsqrtf(var + EPSF);
        float sub  = rstd * mean;
#pragma unroll
        for (int k = 0; k < 4; k++) {
            acc[k * 4 + 0] += rstd * v[t][k].x - sub;
            acc[k * 4 + 1] += rstd * v[t][k].y - sub;
            acc[k * 4 + 2] += rstd * v[t][k].z - sub;
            acc[k * 4 + 3] += rstd * v[t][k].w - sub;
        }
    }
#pragma unroll
    for (int k = 0; k < 4; k++)
        *(float4*)&stg[warp * DD + k * 128 + lane * 4] =
            make_float4(acc[k * 4], acc[k * 4 + 1], acc[k * 4 + 2], acc[k * 4 + 3]);
    __syncthreads();
    float r0 = 0.f, r1 = 0.f;
#pragma unroll
    for (int w = 0; w < 8; w++) {
        r0 += stg[w * DD + tid];
        r1 += stg[w * DD + tid + 256];
    }
    g_part[b][blk][tid]       = r0;
    g_part[b][blk][tid + 256] = r1;
}

// ---------------------------------------------------------------------------
// Fused stage kernel: grid = NMID + 256 blocks, 256 threads, 2 blocks/SM.
// Deadlock-free by construction: dependency is one-way (gates wait on mids),
// and mid blocks (blockIdx 0..NMID) are scheduled first.
//   blocks [0,NMID): mid — per (b,h): fold g_part, ksum, M', S, bias;
//                    fence + atomicAdd(g_flag[st]).
//   blocks [NMID,..): gate — phase A LN stats (overlaps mid), volatile-poll
//                    the flag, __ldcg-load M, dots on L1-hot x, MLP,
//                    write out, atomic-free emit of next g_part.
// ---------------------------------------------------------------------------
__global__ void __launch_bounds__(256, 2)
k_stage(const float* __restrict__ xin, float* xout,
        const float* __restrict__ Wq, const float* __restrict__ Wk,
        const float* __restrict__ lng, const float* __restrict__ lnb,
        const float* __restrict__ W1, const float* __restrict__ b1,
        const float* __restrict__ W2, const float* __restrict__ b2,
        int srcm, const int* __restrict__ emit_kpm, int emit, int st) {
    int tid = threadIdx.x;
    int warp = tid >> 5, lane = tid & 31;
    unsigned hi = lane & 16;

    __shared__ float Msh[HH * DD];             // 16 KB; gate: M + emit staging
    __shared__ float csh[DD];                  // mid: folded c vector
    __shared__ float ksh[DH];
    __shared__ float rs8[8], rb8[8];
    __shared__ float Ssh[HH], Bsh[HH];
    __shared__ float W1sh[128], b1sh[16], W2sh[16];
    __shared__ float b2sh;
    __shared__ int allsh;

    if (blockIdx.x < NMID) {
        // ================= mid block: one (b,h) =================
        int b = blockIdx.x >> 3, h = blockIdx.x & 7;
        float validf = g_valid[srcm][b];
        float cntf = g_all[srcm][b] ? 0.f : validf;

        float a0 = 0.f, a1 = 0.f;
#pragma unroll 8
        for (int g = 0; g < GG; g++) {
            a0 += g_part[b][g][tid];
            a1 += g_part[b][g][tid + 256];
        }
        csh[tid]       = lng[tid] * a0 + cntf * lnb[tid];
        csh[tid + 256] = lng[tid + 256] * a1 + cntf * lnb[tid + 256];
        __syncthreads();

        // ksum: 8 rows per warp, packed pair-reduce
        float rowp[8];
#pragma unroll
        for (int jj = 0; jj < 8; jj++) {
            int j = warp * 8 + jj;
            const float* wk = Wk + (size_t)(h * DH + j) * DD;
            float s = 0.f;
#pragma unroll
            for (int k = 0; k < 16; k++) { int d = lane + 32 * k; s += csh[d] * wk[d]; }
            rowp[jj] = s;
        }
#pragma unroll
        for (int p = 0; p < 4; p++) {
            float r = wsum2_packed(rowp[2 * p], rowp[2 * p + 1], hi);
            if (lane == 0)       ksh[warp * 8 + 2 * p]     = r;
            else if (lane == 16) ksh[warp * 8 + 2 * p + 1] = r;
        }
        __syncthreads();

        float m0 = 0.f, m1 = 0.f;
#pragma unroll
        for (int j = 0; j < DH; j++) {
            float kj = ksh[j];
            const float* wq = Wq + (size_t)(h * DH + j) * DD;
            m0 += kj * wq[tid];
            m1 += kj * wq[tid + 256];
        }
        float inv = 0.125f / validf;
        m0 *= inv; m1 *= inv;
        float mp0 = m0 * lng[tid], mp1 = m1 * lng[tid + 256];
        g_M[b][h][tid]       = mp0;
        g_M[b][h][tid + 256] = mp1;

        float r = wsum2_packed(mp0 + mp1,
                               lnb[tid] * m0 + lnb[tid + 256] * m1, hi);
        if (lane == 0)       rs8[warp] = r;
        else if (lane == 16) rb8[warp] = r;
        __threadfence();              // make this thread's g_M stores visible
        __syncthreads();
        if (tid == 0) {
            float S = 0.f, Bv = 0.f;
            for (int w = 0; w < 8; w++) { S += rs8[w]; Bv += rb8[w]; }
            g_S[b][h] = S;
            g_bias[b][h] = Bv;
            __threadfence();          // release
            atomicAdd(&g_flag[st], 1);
        }
        return;
    }

    // ================= gate block =================
    int blkid = blockIdx.x - NMID;
    int b = blkid >> 6, blk = blkid & 63;

    // prologue: input-constant weights (no dependence on mid)
    if (tid >= 32 && tid < 160) W1sh[tid - 32] = W1[tid - 32];
    if (tid >= 160 && tid < 176) b1sh[tid - 160] = b1[tid - 160];
    if (tid >= 176 && tid < 192) W2sh[tid - 176] = W2[tid - 176];
    if (tid == 192) b2sh = b2[0];
    if (tid == 193) allsh = g_all[srcm][b];

    int t0 = blk * 32 + warp * 4;              // 4 consecutive tokens per warp
    const float4* base = (const float4*)(xin + ((size_t)b * TT + t0) * DD);
    float4* obase = (float4*)(xout + ((size_t)b * TT + t0) * DD);
    const float4* M4 = (const float4*)&Msh[0];
    int eidx = lane & 15;

    // ---- phase A: LN stats, streams x from DRAM (overlaps mid blocks) ----
    float s[4], sq[4];
#pragma unroll
    for (int t = 0; t < 4; t++) { s[t] = 0.f; sq[t] = 0.f; }
#pragma unroll
    for (int k = 0; k < 4; k++) {
#pragma unroll
        for (int t = 0; t < 4; t++) {
            float4 x = base[t * 128 + k * 32 + lane];
            s[t]  += x.x + x.y + x.z + x.w;
            sq[t] += x.x * x.x + x.y * x.y + x.z * x.z + x.w * x.w;
        }
    }
#pragma unroll
    for (int t = 0; t < 4; t++) wsum2(s[t], sq[t], s[t], sq[t], hi);

    // ---- wait for mid completion: volatile poll (no atomic-ALU traffic) ----
    if (tid == 0) {
        volatile int* vf = &g_flag[st];
        while (*vf < NMID) __nanosleep(256);
        __threadfence();              // acquire
    }
    __syncthreads();

    // ---- load M/S/bias (L1-bypass: freshly written by other SMs) ----
    {
        const float4* msrc = (const float4*)&g_M[b][0][0];
        float4* mdst = (float4*)&Msh[0];
#pragma unroll
        for (int i = 0; i < 4; i++) mdst[tid + i * 256] = __ldcg(msrc + tid + i * 256);
        if (tid < HH) { Ssh[tid] = __ldcg(&g_S[b][tid]); Bsh[tid] = __ldcg(&g_bias[b][tid]); }
    }
    __syncthreads();

    // ---- phase B: dots, x re-read (L1-hot) ----
    float dot[4][8];
#pragma unroll
    for (int t = 0; t < 4; t++)
#pragma unroll
        for (int h = 0; h < 8; h++) dot[t][h] = 0.f;
#pragma unroll
    for (int k = 0; k < 4; k++) {
        float4 xv[4];
#pragma unroll
        for (int t = 0; t < 4; t++) xv[t] = base[t * 128 + k * 32 + lane];
#pragma unroll
        for (int h = 0; h < 8; h++) {
            float4 mv = M4[h * 128 + k * 32 + lane];
#pragma unroll
            for (int t = 0; t < 4; t++) {
                dot[t][h] += xv[t].x * mv.x + xv[t].y * mv.y
                           + xv[t].z * mv.z + xv[t].w * mv.w;
            }
        }
    }
#pragma unroll
    for (int t = 0; t < 4; t++)
#pragma unroll
        for (int i = 0; i < 4; i++)
            wsum2(dot[t][i], dot[t][i + 4], dot[t][i], dot[t][i + 4], hi);

    // ---- phase 3: lane-parallel MLP, 4 chains interleaved ----
    float mean[4], var[4], part[4];
#pragma unroll
    for (int t = 0; t < 4; t++) {
        mean[t] = s[t] * (1.f / DD);
        var[t]  = sq[t] * (1.f / DD) - mean[t] * mean[t];
        float rstd = rsqrtf(var[t] + EPSF);
        float a = b1sh[eidx];
#pragma unroll
        for (int h = 0; h < 8; h++) {
            float rel = rstd * (dot[t][h] - mean[t] * Ssh[h]) + Bsh[h];
            a += rel * W1sh[eidx * 8 + h];
        }
        part[t] = fmaxf(a, 0.f) * W2sh[eidx];
    }
    wsum2(part[0], part[1], part[0], part[1], hi);
    wsum2(part[2], part[3], part[2], part[3], hi);

    float factor[4], rf[4], sub2[4];
#pragma unroll
    for (int t = 0; t < 4; t++) {
        float gacc = b2sh + 0.5f * part[t];
        float gate = 1.f / (1.f + expf(-gacc));
        if (allsh) gate = 0.f;
        factor[t] = 1.f + gate;
        float rstd2 = rsqrtf(factor[t] * factor[t] * var[t] + EPSF);
        rf[t]   = rstd2 * factor[t];
        sub2[t] = rf[t] * mean[t];
    }

    // ---- phase C: re-read x (L1-hot), write out, emit partials ----
    float acc[16];
#pragma unroll
    for (int i = 0; i < 16; i++) acc[i] = 0.f;
#pragma unroll
    for (int t = 0; t < 4; t++) {
        int keep = emit ? (emit_kpm[(size_t)b * TT + t0 + t] == 0) : 0;
#pragma unroll
        for (int k = 0; k < 4; k++) {
            float4 x = base[t * 128 + k * 32 + lane];
            float4 o;
            o.x = x.x * factor[t]; o.y = x.y * factor[t];
            o.z = x.z * factor[t]; o.w = x.w * factor[t];
            obase[t * 128 + k * 32 + lane] = o;
            if (keep) {
                acc[k * 4 + 0] += rf[t] * x.x - sub2[t];
                acc[k * 4 + 1] += rf[t] * x.y - sub2[t];
                acc[k * 4 + 2] += rf[t] * x.z - sub2[t];
                acc[k * 4 + 3] += rf[t] * x.w - sub2[t];
            }
        }
    }

    if (emit) {
        __syncthreads();   // Msh reads done; reuse as staging. Safe vs mid:
                           // we passed the flag, so mid finished reading g_part.
#pragma unroll
        for (int k = 0; k < 4; k++)
            *(float4*)&Msh[warp * DD + k * 128 + lane * 4] =
                make_float4(acc[k * 4], acc[k * 4 + 1], acc[k * 4 + 2], acc[k * 4 + 3]);
        __syncthreads();
        float r0 = 0.f, r1 = 0.f;
#pragma unroll
        for (int w = 0; w < 8; w++) {
            r0 += Msh[w * DD + tid];
            r1 += Msh[w * DD + tid + 256];
        }
        g_part[b][blk][tid]       = r0;
        g_part[b][blk][tid + 256] = r1;
    }
}

// ---------------------------------------------------------------------------
extern "C" void kernel_launch(void* const* d_in, const int* in_sizes, int n_in,
                              void* d_out, int out_size) {
    (void)in_sizes; (void)n_in; (void)out_size;
    const float* x_vid = (const float*)d_in[0];
    const float* x_aud = (const float*)d_in[1];
    const int* vid_kpm = (const int*)d_in[2];
    const int* aud_kpm = (const int*)d_in[3];
    const float* Wq_vid = (const float*)d_in[4];
    const float* Wk_aud = (const float*)d_in[5];
    const float* Wq_aud = (const float*)d_in[6];
    const float* Wk_vid = (const float*)d_in[7];
    const float* vgW1 = (const float*)d_in[8];
    const float* vgb1 = (const float*)d_in[9];
    const float* vgW2 = (const float*)d_in[10];
    const float* vgb2 = (const float*)d_in[11];
    const float* agW1 = (const float*)d_in[12];
    const float* agb1 = (const float*)d_in[13];
    const float* agW2 = (const float*)d_in[14];
    const float* agb2 = (const float*)d_in[15];
    const float* vid_g = (const float*)d_in[16];
    const float* vid_b = (const float*)d_in[17];
    const float* aud_g = (const float*)d_in[18];
    const float* aud_b = (const float*)d_in[19];

    const size_t N = (size_t)BB * TT * DD;
    float* out_vid = (float*)d_out;
    float* out_aud = out_vid + N;

    // initial source reduce (LN-sum of x_aud under aud mask) + mask stats
    // + per-stage flag reset (always the first node of a replay)
    k_reduce<<<dim3(GG + 2, BB), 256>>>(x_aud, aud_kpm, vid_kpm, aud_kpm);

    const float* cur_vid = x_vid;
    const float* cur_aud = x_aud;
    int st = 0;
    for (int l = 0; l < LL; l++) {
        size_t wofs = (size_t)l * DD * DD;
        // --- vid stage: source = aud (mask 1); fused mid+gate; emit vid ---
        k_stage<<<NMID + 256, 256>>>(cur_vid, out_vid,
                                     Wq_vid + wofs, Wk_aud + wofs,
                                     vid_g + (size_t)l * DD, vid_b + (size_t)l * DD,
                                     vgW1 + (size_t)l * 128, vgb1 + (size_t)l * 16,
                                     vgW2 + (size_t)l * 16, vgb2 + l,
                                     1, vid_kpm, 1, st++);
        cur_vid = out_vid;
        // --- aud stage: source = updated vid (mask 0); fused mid+gate ---
        int emit_aud = (l < LL - 1) ? 1 : 0;
        k_stage<<<NMID + 256, 256>>>(cur_aud, out_aud,
                                     Wq_aud + wofs, Wk_vid + wofs,
                                     aud_g + (size_t)l * DD, aud_b + (size_t)l * DD,
                                     agW1 + (size_t)l * 128, agb1 + (size_t)l * 16,
                                     agW2 + (size_t)l * 16, agb2 + l,
                                     0, aud_kpm, emit_aud, st++);
        cur_aud = out_aud;
    }
}